// round 14
// baseline (speedup 1.0000x reference)
#include <cuda_runtime.h>
#include <cuda_fp16.h>
#include <cstdint>

#define N_OUT 4096
#define M_IN  4096
#define BATCH 128
#define KTOT  4096
#define BN    64
#define SPLITK 4
#define KPER  (KTOT / SPLITK)   // 1024
#define BK    64
#define KT    (KPER / BK)       // 16
#define STAGES 4
// A stage: 128x64 fp16 = 16KB. B double buffer: 2 x 64x64 fp16 = 2 x 8KB.
#define ASTG_H   8192                      // halves per A stage
#define SMEM_A_BYTES (STAGES * ASTG_H * 2) // 65536
#define SMEM_BYTES   (SMEM_A_BYTES + 2 * 8192)  // 81920

#define NBUCK 4096     // 64 rowblocks x 64 k-tiles
#define BCAP  1024     // entries per bucket (mean 400)

// Device scratch (no allocation allowed)
__device__ __align__(16) uint32_t g_buck[(size_t)NBUCK * BCAP];  // 16MB
__device__ int g_cnt[NBUCK];
__device__ __align__(16) __half g_xh[BATCH * M_IN];              // x in fp16

// ---------------------------------------------------------------------------
__device__ __forceinline__ uint32_t smem_u32(const void* p) {
    return (uint32_t)__cvta_generic_to_shared(p);
}
__device__ __forceinline__ void cpasync16(uint32_t dst, const void* src) {
    asm volatile("cp.async.cg.shared.global [%0], [%1], 16;" :: "r"(dst), "l"(src));
}
__device__ __forceinline__ void ldsm4(uint32_t* r, uint32_t a) {
    asm volatile("ldmatrix.sync.aligned.m8n8.x4.shared.b16 {%0,%1,%2,%3}, [%4];"
                 : "=r"(r[0]), "=r"(r[1]), "=r"(r[2]), "=r"(r[3]) : "r"(a));
}
__device__ __forceinline__ void ldsm2(uint32_t* r, uint32_t a) {
    asm volatile("ldmatrix.sync.aligned.m8n8.x2.shared.b16 {%0,%1}, [%2];"
                 : "=r"(r[0]), "=r"(r[1]) : "r"(a));
}
__device__ __forceinline__ void mma16816(float* c, const uint32_t* a, const uint32_t* b) {
    asm volatile(
        "mma.sync.aligned.m16n8k16.row.col.f32.f16.f16.f32 "
        "{%0,%1,%2,%3}, {%4,%5,%6,%7}, {%8,%9}, {%0,%1,%2,%3};"
        : "+f"(c[0]), "+f"(c[1]), "+f"(c[2]), "+f"(c[3])
        : "r"(a[0]), "r"(a[1]), "r"(a[2]), "r"(a[3]), "r"(b[0]), "r"(b[1]));
}
__device__ __forceinline__ void redv2(float* p, float x, float y) {
    asm volatile("red.global.add.v2.f32 [%0], {%1, %2};"
                 :: "l"(p), "f"(x), "f"(y) : "memory");
}

// ---------------------------------------------------------------------------
// K0: bucket nnz by (row>>6, col>>6); fuse x->fp16 + out=bias.
// g_cnt zeroed by preceding cudaMemsetAsync.
// packed entry: (r&63)<<14 | (c&63)<<8 | (val&0xFF)
// ---------------------------------------------------------------------------
__global__ void k_bucket(const int* __restrict__ val,
                         const int* __restrict__ rows,
                         const int* __restrict__ cols,
                         int nnz,
                         const float* __restrict__ x,
                         const float* __restrict__ bias,
                         float* __restrict__ out) {
    const int gid = blockIdx.x * blockDim.x + threadIdx.x;

    if (gid < nnz) {
        int r = rows[gid];
        int c = cols[gid];
        int v = val[gid];
        int b = ((r >> 6) << 6) | (c >> 6);
        int pos = atomicAdd(&g_cnt[b], 1);
        if (pos < BCAP)
            g_buck[((size_t)b << 10) + pos] =
                ((uint32_t)(r & 63) << 14) | ((uint32_t)(c & 63) << 8)
                | ((uint32_t)v & 0xFF);
    }

    if (gid < (BATCH * M_IN) / 4) {
        const int idx = gid * 4;
        float4 v4 = *reinterpret_cast<const float4*>(x + idx);
        __half2* xp = reinterpret_cast<__half2*>(g_xh + idx);
        xp[0] = __floats2half2_rn(v4.x, v4.y);
        xp[1] = __floats2half2_rn(v4.z, v4.w);
        *reinterpret_cast<float4*>(out + idx) =
            *reinterpret_cast<const float4*>(bias + (idx & (N_OUT - 1)));
    }
}

// ---------------------------------------------------------------------------
// K1: GEMM with B tiles built in smem from buckets.
// Grid (64 rowblocks, SPLITK). CTA: out rows [bx*64,+64), K [by*1024,+1024).
// R13 mainloop config: 4-stage A cp.async, 8 warps 4(m)x2(n), 2 CTAs/SM.
// B double buffer: build B[kt+1] (zero + smem-atomic scatter) after issuing
// MMAs of kt. Per-k-tile bucket = bx*64 + by*16 + kt (mean 400 entries).
// ---------------------------------------------------------------------------
__global__ void __launch_bounds__(256, 2)
k_gemm(const float* __restrict__ scales, float* __restrict__ out) {
    extern __shared__ __align__(1024) char smc[];
    __shared__ int s_cnt[16];

    __half* smA = reinterpret_cast<__half*>(smc);
    __half* smB[2] = { reinterpret_cast<__half*>(smc + SMEM_A_BYTES),
                       reinterpret_cast<__half*>(smc + SMEM_A_BYTES + 8192) };

    const int tid  = threadIdx.x;
    const int lane = tid & 31;
    const int warp = tid >> 5;
    const int wm   = warp & 3;       // 0..3  -> 32-row M strip
    const int wn   = warp >> 2;      // 0..1  -> 32-col N strip
    const int bn0  = blockIdx.x * BN;
    const int kbase = blockIdx.y * KPER;
    const int buck0 = blockIdx.x * 64 + blockIdx.y * 16;

    float acc[2][4][4];
#pragma unroll
    for (int i = 0; i < 2; i++)
#pragma unroll
        for (int j = 0; j < 4; j++)
#pragma unroll
            for (int q = 0; q < 4; q++) acc[i][j][q] = 0.0f;

    // per-thread A load coords: 4 chunks of 16B
    uint32_t aoff[4];
    const __half* asrc[4];
#pragma unroll
    for (int i = 0; i < 4; i++) {
        int q = tid + i * 256;           // 0..1023
        int r = q >> 3, c = q & 7;
        aoff[i] = (r * 64 + ((c ^ (r & 7)) << 3)) * 2;   // byte offset in stage
        asrc[i] = g_xh + r * M_IN + kbase + (c << 3);
    }

    const uint32_t smb = smem_u32(smc);
    auto load_stage = [&](int s, int kofs) {
        uint32_t sb = smb + s * (ASTG_H * 2);
#pragma unroll
        for (int i = 0; i < 4; i++) cpasync16(sb + aoff[i], asrc[i] + kofs);
    };

    // B scatter helper: build tile for global k-tile (buck0+kt) into smB[buf]
    auto scatter_B = [&](int buf, int kt) {
        int cnt = s_cnt[kt];
        __half* Bn = smB[buf];
        const uint32_t* bp = g_buck + ((size_t)(buck0 + kt) << 10);
        for (int i = tid; i < cnt; i += 256) {
            uint32_t pk = bp[i];
            int r6 = (pk >> 14) & 63;
            int c6 = (pk >> 8) & 63;
            int v  = (int)(pk << 24) >> 24;
            int ho = r6 * 64 + ((((c6 >> 3) ^ (r6 & 7)) << 3) | (c6 & 7));
            atomicAdd(&Bn[ho], __float2half_rn((float)v));
        }
    };

    // prologue: counts, zero both B buffers, A stages 0..2, scatter B[0]
    if (tid < 16) {
        int c = g_cnt[buck0 + tid];
        s_cnt[tid] = c < BCAP ? c : BCAP;
    }
    {
        uint4 z; z.x = 0; z.y = 0; z.z = 0; z.w = 0;
        uint4* b4 = reinterpret_cast<uint4*>(smc + SMEM_A_BYTES);
#pragma unroll
        for (int i = 0; i < 4; i++) b4[tid + i * 256] = z;   // 16KB
    }
#pragma unroll
    for (int s = 0; s < STAGES - 1; s++) {
        load_stage(s, s * BK);
        asm volatile("cp.async.commit_group;");
    }
    __syncthreads();
    scatter_B(0, 0);

#pragma unroll 1
    for (int kt = 0; kt < KT; ++kt) {
        asm volatile("cp.async.wait_group %0;" :: "n"(STAGES - 2));
        __syncthreads();   // A stage ready; B[cur] scatter complete

        if (kt + STAGES - 1 < KT)
            load_stage((kt + STAGES - 1) & (STAGES - 1), (kt + STAGES - 1) * BK);
        asm volatile("cp.async.commit_group;");

        const __half* As = smA + (kt & (STAGES - 1)) * ASTG_H;
        const __half* Bs = smB[kt & 1];

#pragma unroll
        for (int ks = 0; ks < 4; ++ks) {
            uint32_t af[2][4];
#pragma unroll
            for (int mi = 0; mi < 2; mi++) {
                int row = wm * 32 + mi * 16 + (lane & 7) + ((lane >> 3) & 1) * 8;
                int ch  = ks * 2 + (lane >> 4);
                ldsm4(af[mi], smem_u32(As + row * 64 + ((ch ^ (row & 7)) << 3)));
            }
#pragma unroll
            for (int ni = 0; ni < 4; ni++) {
                int rowb = wn * 32 + ni * 8 + (lane & 7);
                int chb  = ks * 2 + ((lane >> 3) & 1);
                uint32_t bf[2];
                ldsm2(bf, smem_u32(Bs + rowb * 64 + ((chb ^ (rowb & 7)) << 3)));
#pragma unroll
                for (int mi = 0; mi < 2; mi++)
                    mma16816(acc[mi][ni], af[mi], bf);
            }
        }

        // build B for kt+1 in the other buffer (overlaps MMAs above)
        if (kt + 1 < KT) {
            int nxt = (kt + 1) & 1;
            if (kt >= 1) {
                // zero B[nxt]; its readers (kt-1) finished before this kt's top bar
                uint4 z; z.x = 0; z.y = 0; z.z = 0; z.w = 0;
                uint4* b4 = reinterpret_cast<uint4*>(smB[nxt]);
#pragma unroll
                for (int i = 0; i < 2; i++) b4[tid + i * 256] = z;   // 8KB
                __syncthreads();   // zero visible before scatter
            }
            scatter_B(nxt, kt + 1);
        }
    }

    // epilogue: scale + atomic add into bias-initialized out
#pragma unroll
    for (int ni = 0; ni < 4; ni++) {
        int nq = bn0 + wn * 32 + ni * 8 + ((lane & 3) << 1);
        float s0 = __ldg(scales + nq);
        float s1 = __ldg(scales + nq + 1);
#pragma unroll
        for (int mi = 0; mi < 2; mi++) {
            int r0 = wm * 32 + mi * 16 + (lane >> 2);
            redv2(out + (size_t)r0 * N_OUT + nq,
                  acc[mi][ni][0] * s0, acc[mi][ni][1] * s1);
            redv2(out + (size_t)(r0 + 8) * N_OUT + nq,
                  acc[mi][ni][2] * s0, acc[mi][ni][3] * s1);
        }
    }
}

// ---------------------------------------------------------------------------
extern "C" void kernel_launch(void* const* d_in, const int* in_sizes, int n_in,
                              void* d_out, int out_size) {
    const float* x    = (const float*)d_in[0];
    const int*   wval = (const int*)d_in[1];
    const float* wsc  = (const float*)d_in[2];
    const int*   rows = (const int*)d_in[3];
    const int*   cols = (const int*)d_in[4];
    const float* bias = (const float*)d_in[5];
    float* out = (float*)d_out;
    const int nnz = in_sizes[1];

    cudaFuncSetAttribute(k_gemm, cudaFuncAttributeMaxDynamicSharedMemorySize, SMEM_BYTES);

    // node 1: zero bucket counters (16KB)
    void* cptr = nullptr;
    cudaGetSymbolAddress(&cptr, g_cnt);
    cudaMemsetAsync(cptr, 0, NBUCK * sizeof(int));

    // node 2: bucket nnz + x->fp16 + out=bias
    k_bucket<<<(nnz + 255) / 256, 256>>>(wval, rows, cols, nnz, x, bias, out);

    // node 3: GEMM with in-smem B build
    k_gemm<<<dim3(N_OUT / BN, SPLITK), 256, SMEM_BYTES>>>(wsc, out);
}

// round 15
// speedup vs baseline: 2.8396x; 2.8396x over previous
#include <cuda_runtime.h>
#include <cuda_fp16.h>
#include <cstdint>

#define N_OUT 4096
#define M_IN  4096
#define BATCH 128
#define KTOT  4096
#define BN    64
#define SPLITK 4
#define KPER  (KTOT / SPLITK)   // 1024
#define BK    64
#define KT    (KPER / BK)       // 16
#define STAGES 4
// stage size in halves: A 128x64 + B 64x64 = 12288 halves (24KB)
#define STG_H 12288
#define SMEM_BYTES (STAGES * STG_H * 2)   // 98304

#define ROWS_PER_CTA 4
#define DENSE_SMEM (ROWS_PER_CTA * M_IN * 2)   // 32768

// Scratch (device globals; no allocation allowed)
__device__ __align__(16) __half g_Wh[(size_t)N_OUT * M_IN];   // 32MB dense fp16 W
__device__ __align__(16) __half g_xh[BATCH * M_IN];           // x in fp16
__device__ int g_rstart[N_OUT + 1];                           // row segment starts

// ---------------------------------------------------------------------------
__device__ __forceinline__ uint32_t smem_u32(const void* p) {
    return (uint32_t)__cvta_generic_to_shared(p);
}
__device__ __forceinline__ void cpasync16(uint32_t dst, const void* src) {
    asm volatile("cp.async.cg.shared.global [%0], [%1], 16;" :: "r"(dst), "l"(src));
}
__device__ __forceinline__ void ldsm4(uint32_t* r, uint32_t a) {
    asm volatile("ldmatrix.sync.aligned.m8n8.x4.shared.b16 {%0,%1,%2,%3}, [%4];"
                 : "=r"(r[0]), "=r"(r[1]), "=r"(r[2]), "=r"(r[3]) : "r"(a));
}
__device__ __forceinline__ void mma16816(float* c, const uint32_t* a, const uint32_t* b) {
    asm volatile(
        "mma.sync.aligned.m16n8k16.row.col.f32.f16.f16.f32 "
        "{%0,%1,%2,%3}, {%4,%5,%6,%7}, {%8,%9}, {%0,%1,%2,%3};"
        : "+f"(c[0]), "+f"(c[1]), "+f"(c[2]), "+f"(c[3])
        : "r"(a[0]), "r"(a[1]), "r"(a[2]), "r"(a[3]), "r"(b[0]), "r"(b[1]));
}
__device__ __forceinline__ void redv2(float* p, float x, float y) {
    asm volatile("red.global.add.v2.f32 [%0], {%1, %2};"
                 :: "l"(p), "f"(x), "f"(y) : "memory");
}

// ---------------------------------------------------------------------------
// K0: row segment starts from sorted row_ids (g_rstart[r] = first i with
// rows[i] >= r). Parallel neighbor compare; gap loops are short (random rows).
// ---------------------------------------------------------------------------
__global__ void k_scan(const int* __restrict__ rows, int nnz) {
    const int i = blockIdx.x * blockDim.x + threadIdx.x;
    if (i >= nnz) return;
    int r1 = rows[i];
    if (i == 0) {
        for (int r = 0; r <= r1; r++) g_rstart[r] = 0;
    } else {
        int r0 = rows[i - 1];
        for (int r = r0 + 1; r <= r1; r++) g_rstart[r] = i;
    }
    if (i == nnz - 1) {
        for (int r = r1 + 1; r <= N_OUT; r++) g_rstart[r] = nnz;
    }
}

// ---------------------------------------------------------------------------
// K1: build dense W rows in smem (exact fp16 integer accumulate), write out
// coalesced. Also (first 128 CTAs) x->fp16 + out=bias.
// CTA b: rows [4b, 4b+4), segment [g_rstart[4b], g_rstart[4b+4)).
// ---------------------------------------------------------------------------
__global__ void __launch_bounds__(256)
k_dense(const int* __restrict__ val,
        const int* __restrict__ rows,
        const int* __restrict__ cols,
        const float* __restrict__ x,
        const float* __restrict__ bias,
        float* __restrict__ out) {
    extern __shared__ __align__(16) __half sW[];   // 4 rows x 4096 halves
    const int tid = threadIdx.x;
    const int r0 = blockIdx.x * ROWS_PER_CTA;

    // zero the 32KB row-block (2048 uint4)
    uint4* s4 = reinterpret_cast<uint4*>(sW);
    uint4 z; z.x = 0; z.y = 0; z.z = 0; z.w = 0;
#pragma unroll
    for (int j = 0; j < 8; j++) s4[tid + j * 256] = z;

    // fused x->fp16 + out=bias (first 32768 global threads)
    const int gid = blockIdx.x * 256 + tid;
    if (gid < (BATCH * M_IN) / 4) {
        const int idx = gid * 4;
        float4 v4 = *reinterpret_cast<const float4*>(x + idx);
        __half2* xp = reinterpret_cast<__half2*>(g_xh + idx);
        xp[0] = __floats2half2_rn(v4.x, v4.y);
        xp[1] = __floats2half2_rn(v4.z, v4.w);
        *reinterpret_cast<float4*>(out + idx) =
            *reinterpret_cast<const float4*>(bias + (idx & (N_OUT - 1)));
    }
    __syncthreads();

    // accumulate this CTA's nnz segment into smem (spread addresses, exact)
    const int lo = g_rstart[r0];
    const int hi = g_rstart[r0 + ROWS_PER_CTA];
    for (int i = lo + tid; i < hi; i += 256) {
        int rr = rows[i] - r0;
        int c  = cols[i];
        atomicAdd(&sW[rr * M_IN + c], __float2half_rn((float)val[i]));
    }
    __syncthreads();

    // coalesced write of 4 complete rows (32KB)
    uint4* w4 = reinterpret_cast<uint4*>(g_Wh + (size_t)r0 * M_IN);
#pragma unroll
    for (int j = 0; j < 8; j++) w4[tid + j * 256] = s4[tid + j * 256];
}

// ---------------------------------------------------------------------------
// K2: GEMM  out[b,n] += scale[n] * sum_k x_h[b,k] * W[n,k]
// Byte-identical to R13 (best measured: 22.1us).
// ---------------------------------------------------------------------------
__global__ void __launch_bounds__(256, 2)
k_gemm(const float* __restrict__ scales, float* __restrict__ out) {
    extern __shared__ __align__(1024) __half sm[];

    const int tid  = threadIdx.x;
    const int lane = tid & 31;
    const int warp = tid >> 5;
    const int wm   = warp & 3;       // 0..3  -> 32-row M strip
    const int wn   = warp >> 2;      // 0..1  -> 32-col N strip
    const int bn0  = blockIdx.x * BN;
    const int kbase = blockIdx.y * KPER;

    float acc[2][4][4];
#pragma unroll
    for (int i = 0; i < 2; i++)
#pragma unroll
        for (int j = 0; j < 4; j++)
#pragma unroll
            for (int q = 0; q < 4; q++) acc[i][j][q] = 0.0f;

    uint32_t aoff[4], boff[2];
    const __half* asrc[4];
    const __half* bsrc[2];
#pragma unroll
    for (int i = 0; i < 4; i++) {
        int q = tid + i * 256;
        int r = q >> 3, c = q & 7;
        aoff[i] = (r * 64 + ((c ^ (r & 7)) << 3)) * 2;
        asrc[i] = g_xh + r * M_IN + kbase + (c << 3);
    }
#pragma unroll
    for (int i = 0; i < 2; i++) {
        int q = tid + i * 256;
        int r = q >> 3, c = q & 7;
        boff[i] = (8192 + r * 64 + ((c ^ (r & 7)) << 3)) * 2;
        bsrc[i] = g_Wh + (size_t)(bn0 + r) * M_IN + kbase + (c << 3);
    }

    const uint32_t smb = smem_u32(sm);

    auto load_stage = [&](int s, int kofs) {
        uint32_t sb = smb + s * (STG_H * 2);
#pragma unroll
        for (int i = 0; i < 4; i++) cpasync16(sb + aoff[i], asrc[i] + kofs);
#pragma unroll
        for (int i = 0; i < 2; i++) cpasync16(sb + boff[i], bsrc[i] + kofs);
    };

    // B ldsm4 fragment coords: call c covers ni = 2c, 2c+1.
    int b_row[2], b_h;
    {
        int g = lane >> 3;
        b_h = g & 1;
#pragma unroll
        for (int c = 0; c < 2; c++) {
            int ni = 2 * c + (g >> 1);
            b_row[c] = wn * 32 + ni * 8 + (lane & 7);
        }
    }

#pragma unroll
    for (int s = 0; s < STAGES - 1; s++) {
        load_stage(s, s * BK);
        asm volatile("cp.async.commit_group;");
    }

#pragma unroll 1
    for (int kt = 0; kt < KT; ++kt) {
        asm volatile("cp.async.wait_group %0;" :: "n"(STAGES - 2));
        __syncthreads();

        if (kt + STAGES - 1 < KT)
            load_stage((kt + STAGES - 1) & (STAGES - 1), (kt + STAGES - 1) * BK);
        asm volatile("cp.async.commit_group;");

        const __half* As = sm + (kt & (STAGES - 1)) * STG_H;
        const __half* Bs = As + 8192;

#pragma unroll
        for (int ks = 0; ks < 4; ++ks) {
            uint32_t af[2][4];
#pragma unroll
            for (int mi = 0; mi < 2; mi++) {
                int row = wm * 32 + mi * 16 + (lane & 7) + ((lane >> 3) & 1) * 8;
                int ch  = ks * 2 + (lane >> 4);
                ldsm4(af[mi], smem_u32(As + row * 64 + ((ch ^ (row & 7)) << 3)));
            }
            uint32_t bf[2][4];
#pragma unroll
            for (int c = 0; c < 2; c++) {
                int row = b_row[c];
                int ch  = ks * 2 + b_h;
                ldsm4(bf[c], smem_u32(Bs + row * 64 + ((ch ^ (row & 7)) << 3)));
            }
#pragma unroll
            for (int ni = 0; ni < 4; ni++) {
                const uint32_t* bp = &bf[ni >> 1][(ni & 1) * 2];
#pragma unroll
                for (int mi = 0; mi < 2; mi++)
                    mma16816(acc[mi][ni], af[mi], bp);
            }
        }
    }

#pragma unroll
    for (int ni = 0; ni < 4; ni++) {
        int nq = bn0 + wn * 32 + ni * 8 + ((lane & 3) << 1);
        float s0 = __ldg(scales + nq);
        float s1 = __ldg(scales + nq + 1);
#pragma unroll
        for (int mi = 0; mi < 2; mi++) {
            int r0 = wm * 32 + mi * 16 + (lane >> 2);
            redv2(out + (size_t)r0 * N_OUT + nq,
                  acc[mi][ni][0] * s0, acc[mi][ni][1] * s1);
            redv2(out + (size_t)(r0 + 8) * N_OUT + nq,
                  acc[mi][ni][2] * s0, acc[mi][ni][3] * s1);
        }
    }
}

// ---------------------------------------------------------------------------
extern "C" void kernel_launch(void* const* d_in, const int* in_sizes, int n_in,
                              void* d_out, int out_size) {
    const float* x    = (const float*)d_in[0];
    const int*   wval = (const int*)d_in[1];
    const float* wsc  = (const float*)d_in[2];
    const int*   rows = (const int*)d_in[3];
    const int*   cols = (const int*)d_in[4];
    const float* bias = (const float*)d_in[5];
    float* out = (float*)d_out;
    const int nnz = in_sizes[1];

    cudaFuncSetAttribute(k_gemm, cudaFuncAttributeMaxDynamicSharedMemorySize, SMEM_BYTES);

    // node 1: row segment starts
    k_scan<<<(nnz + 255) / 256, 256>>>(rows, nnz);

    // node 2: build dense W coalesced + x->fp16 + out=bias
    k_dense<<<N_OUT / ROWS_PER_CTA, 256, DENSE_SMEM>>>(wval, rows, cols, x, bias, out);

    // node 3: tensor-core GEMM (R13)
    k_gemm<<<dim3(N_OUT / BN, SPLITK), 256, SMEM_BYTES>>>(wsc, out);
}

// round 17
// speedup vs baseline: 2.9974x; 1.0556x over previous
#include <cuda_runtime.h>
#include <cuda_fp16.h>
#include <cstdint>

#define N_OUT 4096
#define M_IN  4096
#define BATCH 128
#define KTOT  4096
#define BN    64
#define SPLITK 4
#define KPER  (KTOT / SPLITK)   // 1024
#define BK    64
#define KT    (KPER / BK)       // 16
#define STAGES 4
// stage size in halves: A 128x64 + B 64x64 = 12288 halves (24KB)
#define STG_H 12288
#define SMEM_BYTES (STAGES * STG_H * 2)   // 98304

#define ROWS_PER_CTA 4
#define DENSE_SMEM (ROWS_PER_CTA * M_IN * 2)   // 32768

// Scratch (device globals; no allocation allowed)
__device__ __align__(16) __half g_Wh[(size_t)N_OUT * M_IN];   // 32MB dense fp16 W
__device__ __align__(16) __half g_xh[BATCH * M_IN];           // x in fp16
__device__ int g_rstart[N_OUT + 1];                           // row segment starts

// ---------------------------------------------------------------------------
__device__ __forceinline__ uint32_t smem_u32(const void* p) {
    return (uint32_t)__cvta_generic_to_shared(p);
}
__device__ __forceinline__ void cpasync16(uint32_t dst, const void* src) {
    asm volatile("cp.async.cg.shared.global [%0], [%1], 16;" :: "r"(dst), "l"(src));
}
__device__ __forceinline__ void ldsm4(uint32_t* r, uint32_t a) {
    asm volatile("ldmatrix.sync.aligned.m8n8.x4.shared.b16 {%0,%1,%2,%3}, [%4];"
                 : "=r"(r[0]), "=r"(r[1]), "=r"(r[2]), "=r"(r[3]) : "r"(a));
}
__device__ __forceinline__ void mma16816(float* c, const uint32_t* a, const uint32_t* b) {
    asm volatile(
        "mma.sync.aligned.m16n8k16.row.col.f32.f16.f16.f32 "
        "{%0,%1,%2,%3}, {%4,%5,%6,%7}, {%8,%9}, {%0,%1,%2,%3};"
        : "+f"(c[0]), "+f"(c[1]), "+f"(c[2]), "+f"(c[3])
        : "r"(a[0]), "r"(a[1]), "r"(a[2]), "r"(a[3]), "r"(b[0]), "r"(b[1]));
}
__device__ __forceinline__ void redv2(float* p, float x, float y) {
    asm volatile("red.global.add.v2.f32 [%0], {%1, %2};"
                 :: "l"(p), "f"(x), "f"(y) : "memory");
}

// ---------------------------------------------------------------------------
// K0: row segment starts from sorted row_ids, 8 elements per thread.
// g_rstart[r] = first index i with rows[i] >= r.
// ---------------------------------------------------------------------------
__global__ void k_scan(const int* __restrict__ rows, int nnz) {
    const int t = blockIdx.x * blockDim.x + threadIdx.x;
    const int base = t * 8;
    if (base >= nnz) return;

    int4 a = *reinterpret_cast<const int4*>(rows + base);
    int4 b = *reinterpret_cast<const int4*>(rows + base + 4);
    int v[9];
    v[0] = (base == 0) ? -1 : rows[base - 1];
    v[1] = a.x; v[2] = a.y; v[3] = a.z; v[4] = a.w;
    v[5] = b.x; v[6] = b.y; v[7] = b.z; v[8] = b.w;

#pragma unroll
    for (int j = 0; j < 8; j++) {
        for (int r = v[j] + 1; r <= v[j + 1]; r++)
            g_rstart[r] = base + j;
    }
    if (base + 8 == nnz) {
        for (int r = v[8] + 1; r <= N_OUT; r++) g_rstart[r] = nnz;
    }
}

// ---------------------------------------------------------------------------
// K1: build dense W rows in smem (exact fp16 integer accumulate), write out
// coalesced. Also (first 128 CTAs) x->fp16 + out=bias.  (identical to R15)
// ---------------------------------------------------------------------------
__global__ void __launch_bounds__(256)
k_dense(const int* __restrict__ val,
        const int* __restrict__ rows,
        const int* __restrict__ cols,
        const float* __restrict__ x,
        const float* __restrict__ bias,
        float* __restrict__ out) {
    extern __shared__ __align__(16) __half sW[];   // 4 rows x 4096 halves
    const int tid = threadIdx.x;
    const int r0 = blockIdx.x * ROWS_PER_CTA;

    uint4* s4 = reinterpret_cast<uint4*>(sW);
    uint4 z; z.x = 0; z.y = 0; z.z = 0; z.w = 0;
#pragma unroll
    for (int j = 0; j < 8; j++) s4[tid + j * 256] = z;

    const int gid = blockIdx.x * 256 + tid;
    if (gid < (BATCH * M_IN) / 4) {
        const int idx = gid * 4;
        float4 v4 = *reinterpret_cast<const float4*>(x + idx);
        __half2* xp = reinterpret_cast<__half2*>(g_xh + idx);
        xp[0] = __floats2half2_rn(v4.x, v4.y);
        xp[1] = __floats2half2_rn(v4.z, v4.w);
        *reinterpret_cast<float4*>(out + idx) =
            *reinterpret_cast<const float4*>(bias + (idx & (N_OUT - 1)));
    }
    __syncthreads();

    const int lo = g_rstart[r0];
    const int hi = g_rstart[r0 + ROWS_PER_CTA];
    for (int i = lo + tid; i < hi; i += 256) {
        int rr = rows[i] - r0;
        int c  = cols[i];
        atomicAdd(&sW[rr * M_IN + c], __float2half_rn((float)val[i]));
    }
    __syncthreads();

    uint4* w4 = reinterpret_cast<uint4*>(g_Wh + (size_t)r0 * M_IN);
#pragma unroll
    for (int j = 0; j < 8; j++) w4[tid + j * 256] = s4[tid + j * 256];
}

// ---------------------------------------------------------------------------
// K2: GEMM  out[b,n] += scale[n] * sum_k x_h[b,k] * W[n,k]
// Byte-identical to R13 (best measured: 22.1us).
// ---------------------------------------------------------------------------
__global__ void __launch_bounds__(256, 2)
k_gemm(const float* __restrict__ scales, float* __restrict__ out) {
    extern __shared__ __align__(1024) __half sm[];

    const int tid  = threadIdx.x;
    const int lane = tid & 31;
    const int warp = tid >> 5;
    const int wm   = warp & 3;       // 0..3  -> 32-row M strip
    const int wn   = warp >> 2;      // 0..1  -> 32-col N strip
    const int bn0  = blockIdx.x * BN;
    const int kbase = blockIdx.y * KPER;

    float acc[2][4][4];
#pragma unroll
    for (int i = 0; i < 2; i++)
#pragma unroll
        for (int j = 0; j < 4; j++)
#pragma unroll
            for (int q = 0; q < 4; q++) acc[i][j][q] = 0.0f;

    uint32_t aoff[4], boff[2];
    const __half* asrc[4];
    const __half* bsrc[2];
#pragma unroll
    for (int i = 0; i < 4; i++) {
        int q = tid + i * 256;
        int r = q >> 3, c = q & 7;
        aoff[i] = (r * 64 + ((c ^ (r & 7)) << 3)) * 2;
        asrc[i] = g_xh + r * M_IN + kbase + (c << 3);
    }
#pragma unroll
    for (int i = 0; i < 2; i++) {
        int q = tid + i * 256;
        int r = q >> 3, c = q & 7;
        boff[i] = (8192 + r * 64 + ((c ^ (r & 7)) << 3)) * 2;
        bsrc[i] = g_Wh + (size_t)(bn0 + r) * M_IN + kbase + (c << 3);
    }

    const uint32_t smb = smem_u32(sm);

    auto load_stage = [&](int s, int kofs) {
        uint32_t sb = smb + s * (STG_H * 2);
#pragma unroll
        for (int i = 0; i < 4; i++) cpasync16(sb + aoff[i], asrc[i] + kofs);
#pragma unroll
        for (int i = 0; i < 2; i++) cpasync16(sb + boff[i], bsrc[i] + kofs);
    };

    int b_row[2], b_h;
    {
        int g = lane >> 3;
        b_h = g & 1;
#pragma unroll
        for (int c = 0; c < 2; c++) {
            int ni = 2 * c + (g >> 1);
            b_row[c] = wn * 32 + ni * 8 + (lane & 7);
        }
    }

#pragma unroll
    for (int s = 0; s < STAGES - 1; s++) {
        load_stage(s, s * BK);
        asm volatile("cp.async.commit_group;");
    }

#pragma unroll 1
    for (int kt = 0; kt < KT; ++kt) {
        asm volatile("cp.async.wait_group %0;" :: "n"(STAGES - 2));
        __syncthreads();

        if (kt + STAGES - 1 < KT)
            load_stage((kt + STAGES - 1) & (STAGES - 1), (kt + STAGES - 1) * BK);
        asm volatile("cp.async.commit_group;");

        const __half* As = sm + (kt & (STAGES - 1)) * STG_H;
        const __half* Bs = As + 8192;

#pragma unroll
        for (int ks = 0; ks < 4; ++ks) {
            uint32_t af[2][4];
#pragma unroll
            for (int mi = 0; mi < 2; mi++) {
                int row = wm * 32 + mi * 16 + (lane & 7) + ((lane >> 3) & 1) * 8;
                int ch  = ks * 2 + (lane >> 4);
                ldsm4(af[mi], smem_u32(As + row * 64 + ((ch ^ (row & 7)) << 3)));
            }
            uint32_t bf[2][4];
#pragma unroll
            for (int c = 0; c < 2; c++) {
                int row = b_row[c];
                int ch  = ks * 2 + b_h;
                ldsm4(bf[c], smem_u32(Bs + row * 64 + ((ch ^ (row & 7)) << 3)));
            }
#pragma unroll
            for (int ni = 0; ni < 4; ni++) {
                const uint32_t* bp = &bf[ni >> 1][(ni & 1) * 2];
#pragma unroll
                for (int mi = 0; mi < 2; mi++)
                    mma16816(acc[mi][ni], af[mi], bp);
            }
        }
    }

#pragma unroll
    for (int ni = 0; ni < 4; ni++) {
        int nq = bn0 + wn * 32 + ni * 8 + ((lane & 3) << 1);
        float s0 = __ldg(scales + nq);
        float s1 = __ldg(scales + nq + 1);
#pragma unroll
        for (int mi = 0; mi < 2; mi++) {
            int r0 = wm * 32 + mi * 16 + (lane >> 2);
            redv2(out + (size_t)r0 * N_OUT + nq,
                  acc[mi][ni][0] * s0, acc[mi][ni][1] * s1);
            redv2(out + (size_t)(r0 + 8) * N_OUT + nq,
                  acc[mi][ni][2] * s0, acc[mi][ni][3] * s1);
        }
    }
}

// ---------------------------------------------------------------------------
extern "C" void kernel_launch(void* const* d_in, const int* in_sizes, int n_in,
                              void* d_out, int out_size) {
    const float* x    = (const float*)d_in[0];
    const int*   wval = (const int*)d_in[1];
    const float* wsc  = (const float*)d_in[2];
    const int*   rows = (const int*)d_in[3];
    const int*   cols = (const int*)d_in[4];
    const float* bias = (const float*)d_in[5];
    float* out = (float*)d_out;
    const int nnz = in_sizes[1];

    cudaFuncSetAttribute(k_gemm, cudaFuncAttributeMaxDynamicSharedMemorySize, SMEM_BYTES);

    // node 1: row segment starts (8 elems/thread)
    k_scan<<<((nnz + 7) / 8 + 255) / 256, 256>>>(rows, nnz);

    // node 2: build dense W coalesced + x->fp16 + out=bias
    k_dense<<<N_OUT / ROWS_PER_CTA, 256, DENSE_SMEM>>>(wval, rows, cols, x, bias, out);

    // node 3: tensor-core GEMM (R13)
    k_gemm<<<dim3(N_OUT / BN, SPLITK), 256, SMEM_BYTES>>>(wsc, out);
}